// round 15
// baseline (speedup 1.0000x reference)
#include <cuda_runtime.h>
#include <cuda_fp16.h>
#include <cstdint>

// Problem constants
#define S_TOK   4096
#define NSLOT   8192
#define DM      768
#define DF      3072
#define NE      8

#define BM 128
#define BN 128
#define BK 64
#define ASTR 72            // A smem stride in halves
#define BSTR 136           // B smem stride in halves

#define N_OUT4 (S_TOK * DM / 4)
#define NW4    (NE * DM * DF / 4)
#define NW8    (NW4 / 2)

#define GATE_BLKS 512
#define CONV_BLKS 4096
#define W2_XTRA   4        // extra grid-x tiles on GEMM1 for W2 conversion + out zero

// ---- scratch (device globals; no allocation allowed) ----
__device__ int    g_count[NE];
__device__ int    g_ticket;
__device__ int    g_list[NE][NSLOT];
__device__ float  g_sw[NSLOT];
__device__ __half g_xh[(size_t)S_TOK * DM];
__device__ __half g_w1h[(size_t)NE * DM * DF];
__device__ __half g_w2h[(size_t)NE * DF * DM];
__device__ __half g_h[(size_t)NSLOT * DF];

__device__ __forceinline__ uint2 cvt4(const float4 v) {
    __half2 a = __floats2half2_rn(v.x, v.y);
    __half2 b = __floats2half2_rn(v.z, v.w);
    uint2 pk;
    pk.x = *(const unsigned*)&a;
    pk.y = *(const unsigned*)&b;
    return pk;
}

// ---------------------------------------------------------------------------
// fused gate(+x convert) + W1 convert
//   blocks [0, GATE_BLKS): gate, warp per token; converts its x row to g_xh
//   blocks [GATE_BLKS, ...): W1 f32->f16, 32B read / 16B write per iteration
// g_count is reset by GEMM2's tail ticket (zero-initialized on first call).
// ---------------------------------------------------------------------------
__global__ void __launch_bounds__(256) gate_prep_kernel(const float* __restrict__ x,
                                                        const float* __restrict__ Wg,
                                                        const float* __restrict__ W1) {
    if (blockIdx.x >= GATE_BLKS) {
        const int cb = blockIdx.x - GATE_BLKS;
        const int t0 = cb * 256 + threadIdx.x;
        const int NT = CONV_BLKS * 256;
        const float4* src = (const float4*)W1;
        uint4* dst = (uint4*)g_w1h;
#pragma unroll 2
        for (int i = t0; i < NW8; i += NT) {
            float4 a = src[2 * i];
            float4 b = src[2 * i + 1];
            uint2 pa = cvt4(a);
            uint2 pb = cvt4(b);
            dst[i] = make_uint4(pa.x, pa.y, pb.x, pb.y);
        }
        return;
    }

    int warp = threadIdx.x >> 5;
    int lane = threadIdx.x & 31;
    int s = blockIdx.x * 8 + warp;
    if (s >= S_TOK) return;

    const float4* xr4 = (const float4*)(x + (size_t)s * DM);
    uint2* xh2 = (uint2*)(g_xh + (size_t)s * DM);

    float acc[NE];
#pragma unroll
    for (int e = 0; e < NE; e++) acc[e] = 0.f;

#pragma unroll
    for (int i = 0; i < DM / 128; i++) {            // 6 float4 per lane
        int q = lane + i * 32;
        float4 v = xr4[q];
        const float* wr = Wg + q * 4 * NE;
#pragma unroll
        for (int e = 0; e < NE; e++) {
            acc[e] += v.x * wr[e] + v.y * wr[NE + e]
                    + v.z * wr[2 * NE + e] + v.w * wr[3 * NE + e];
        }
        xh2[q] = cvt4(v);                           // inline f32->f16 of x
    }
#pragma unroll
    for (int e = 0; e < NE; e++) {
#pragma unroll
        for (int o = 16; o > 0; o >>= 1) {
            acc[e] += __shfl_xor_sync(0xffffffffu, acc[e], o);
        }
    }

    if (lane == 0) {
        int a = 0;
#pragma unroll
        for (int e = 1; e < NE; e++) {
            if (acc[e] > acc[a]) a = e;
        }
        int b = (a == 0) ? 1 : 0;
#pragma unroll
        for (int e = 0; e < NE; e++) {
            if (e != a && acc[e] > acc[b]) b = e;
        }

        float eb = __expf(acc[b] - acc[a]);
        float inv = 1.f / (1.f + eb);
        g_sw[s] = inv;
        g_sw[S_TOK + s] = eb * inv;

        int pa = atomicAdd(&g_count[a], 1);
        g_list[a][pa] = s;
        int pb = atomicAdd(&g_count[b], 1);
        g_list[b][pb] = S_TOK + s;
    }
}

// ---------------------------------------------------------------------------
// tensor-core + cp.async helpers
// ---------------------------------------------------------------------------
__device__ __forceinline__ void ldsm_x4(unsigned& r0, unsigned& r1,
                                        unsigned& r2, unsigned& r3,
                                        const void* p) {
    unsigned a = (unsigned)__cvta_generic_to_shared(p);
    asm volatile("ldmatrix.sync.aligned.m8n8.x4.shared.b16 {%0,%1,%2,%3}, [%4];\n"
                 : "=r"(r0), "=r"(r1), "=r"(r2), "=r"(r3) : "r"(a));
}

__device__ __forceinline__ void ldsm_x4_t(unsigned& r0, unsigned& r1,
                                          unsigned& r2, unsigned& r3,
                                          const void* p) {
    unsigned a = (unsigned)__cvta_generic_to_shared(p);
    asm volatile("ldmatrix.sync.aligned.m8n8.x4.trans.shared.b16 {%0,%1,%2,%3}, [%4];\n"
                 : "=r"(r0), "=r"(r1), "=r"(r2), "=r"(r3) : "r"(a));
}

__device__ __forceinline__ void mma16816(float* c, const unsigned* a, const unsigned* b) {
    asm volatile(
        "mma.sync.aligned.m16n8k16.row.col.f32.f16.f16.f32 "
        "{%0,%1,%2,%3}, {%4,%5,%6,%7}, {%8,%9}, {%0,%1,%2,%3};\n"
        : "+f"(c[0]), "+f"(c[1]), "+f"(c[2]), "+f"(c[3])
        : "r"(a[0]), "r"(a[1]), "r"(a[2]), "r"(a[3]), "r"(b[0]), "r"(b[1]));
}

__device__ __forceinline__ void cp_async16(void* smem_ptr, const void* gptr, bool valid) {
    unsigned saddr = (unsigned)__cvta_generic_to_shared(smem_ptr);
    int sz = valid ? 16 : 0;
    asm volatile("cp.async.cg.shared.global [%0], [%1], 16, %2;\n"
                 :: "r"(saddr), "l"(gptr), "r"(sz));
}
__device__ __forceinline__ void cp_commit() {
    asm volatile("cp.async.commit_group;\n");
}
template<int N>
__device__ __forceinline__ void cp_wait() {
    asm volatile("cp.async.wait_group %0;\n" :: "n"(N));
}

// ---------------------------------------------------------------------------
// Grouped GEMM, 128x128x64 tile, 64x32 warp tiles, 2-stage pipeline, 2 CTA/SM.
//   GEMM1 (+FUSECONV): A = g_xh[slot & (S-1)], W = g_w1h -> relu -> g_h (half);
//                      extra grid-x blocks convert W2 f32->f16 and zero `out`.
//   GEMM2 (+RESET): A = g_h[slot], W = g_w2h -> w*(.+b2) atomicAdd -> out;
//                   last CTA (ticket) resets g_count for the next replay.
// ---------------------------------------------------------------------------
template<int KDIM, int NDIM, bool GEMM1, bool FUSECONV, bool RESET>
__global__ void __launch_bounds__(256, 2) moe_gemm(const float* __restrict__ bias,
                                                   float* __restrict__ out,
                                                   const float* __restrict__ wsrc) {
    constexpr int NTX = NDIM / BN;
    constexpr int A_ST_ELEM = BM * ASTR;
    constexpr int B_ST_ELEM = BK * BSTR;

    if (FUSECONV && blockIdx.x >= NTX) {
        // side-channel: W2 f32->f16 convert + zero `out` (overlaps GEMM1 compute)
        const int cid = ((blockIdx.x - NTX) * gridDim.y + blockIdx.y) * gridDim.z + blockIdx.z;
        const int t0 = cid * 256 + threadIdx.x;
        const int NT = W2_XTRA * (NSLOT / BM) * NE * 256;
        const float4* src = (const float4*)wsrc;
        uint4* dst = (uint4*)g_w2h;
#pragma unroll 2
        for (int i = t0; i < NW8; i += NT) {
            float4 a = src[2 * i];
            float4 b = src[2 * i + 1];
            uint2 pa = cvt4(a);
            uint2 pb = cvt4(b);
            dst[i] = make_uint4(pa.x, pa.y, pb.x, pb.y);
        }
#pragma unroll 2
        for (int i = t0; i < N_OUT4; i += NT) {
            ((float4*)out)[i] = make_float4(0.f, 0.f, 0.f, 0.f);
        }
        return;
    }

    const int e = blockIdx.z;
    const int cnt = g_count[e];
    const int row0 = blockIdx.y * BM;

    if (row0 >= cnt) {
        if (RESET) {
            if (threadIdx.x == 0) {
                int total = (int)(gridDim.x * gridDim.y * gridDim.z);
                int t = atomicAdd(&g_ticket, 1);
                if (t == total - 1) {
#pragma unroll
                    for (int i = 0; i < NE; i++) g_count[i] = 0;
                    g_ticket = 0;
                }
            }
        }
        return;
    }
    const int f0 = blockIdx.x * BN;

    extern __shared__ __half dyn[];
    __half* Asb = dyn;                        // [2][BM][ASTR]
    __half* Bsb = dyn + 2 * A_ST_ELEM;        // [2][BK][BSTR]
    __shared__ int rows_s[BM];

    const int tid = threadIdx.x;
    const int lane = tid & 31;
    const int wid = tid >> 5;
    const int wm = (wid >> 2) * 64;
    const int wn = (wid & 3) * 32;

    if (tid < BM) {
        int r = row0 + tid;
        rows_s[tid] = (r < cnt) ? g_list[e][r] : -1;
    }
    __syncthreads();

    const __half* Ab = GEMM1 ? g_xh : g_h;
    const __half* Wb = (GEMM1 ? g_w1h : g_w2h) + (size_t)e * KDIM * NDIM;

    int a_r[4], a_kq[4], a_slot[4];
#pragma unroll
    for (int l = 0; l < 4; l++) {
        int u = tid + l * 256;
        a_r[l] = u >> 3;
        a_kq[l] = u & 7;
        a_slot[l] = rows_s[a_r[l]];
    }
    int b_kr[4], b_cq[4];
#pragma unroll
    for (int l = 0; l < 4; l++) {
        int u = tid + l * 256;
        b_kr[l] = u >> 4;
        b_cq[l] = u & 15;
    }

    const int NK = KDIM / BK;

    auto load_tile = [&](int buf, int kt) {
        __half* As = Asb + buf * A_ST_ELEM;
        __half* Bs = Bsb + buf * B_ST_ELEM;
#pragma unroll
        for (int l = 0; l < 4; l++) {
            int slot = a_slot[l];
            const __half* src = Ab;
            bool v = (slot >= 0);
            if (v) {
                int arow = GEMM1 ? (slot & (S_TOK - 1)) : slot;
                src = Ab + (size_t)arow * KDIM + kt + a_kq[l] * 8;
            }
            cp_async16(As + a_r[l] * ASTR + a_kq[l] * 8, src, v);
        }
#pragma unroll
        for (int l = 0; l < 4; l++) {
            const __half* src = Wb + (size_t)(kt + b_kr[l]) * NDIM + f0 + b_cq[l] * 8;
            cp_async16(Bs + b_kr[l] * BSTR + b_cq[l] * 8, src, true);
        }
    };

    float c[4][4][4];
#pragma unroll
    for (int mi = 0; mi < 4; mi++) {
#pragma unroll
        for (int ni = 0; ni < 4; ni++) {
#pragma unroll
            for (int q = 0; q < 4; q++) {
                c[mi][ni][q] = 0.f;
            }
        }
    }

    load_tile(0, 0);
    cp_commit();

    for (int k = 0; k < NK; k++) {
        cp_wait<0>();
        __syncthreads();

        if (k + 1 < NK) {
            load_tile((k + 1) & 1, (k + 1) * BK);
            cp_commit();
        }

        const int buf = k & 1;
        const __half* As = Asb + buf * A_ST_ELEM;
        const __half* Bs = Bsb + buf * B_ST_ELEM;
#pragma unroll
        for (int kc = 0; kc < BK; kc += 16) {
            unsigned af[4][4];
            unsigned bf[4][2];
#pragma unroll
            for (int mi = 0; mi < 4; mi++) {
                ldsm_x4(af[mi][0], af[mi][1], af[mi][2], af[mi][3],
                        As + (wm + mi * 16 + (lane & 15)) * ASTR + kc + (lane >> 4) * 8);
            }
#pragma unroll
            for (int nj = 0; nj < 2; nj++) {
                ldsm_x4_t(bf[2 * nj][0], bf[2 * nj][1],
                          bf[2 * nj + 1][0], bf[2 * nj + 1][1],
                          Bs + (kc + (lane & 15)) * BSTR + wn + nj * 16 + (lane >> 4) * 8);
            }
#pragma unroll
            for (int mi = 0; mi < 4; mi++) {
#pragma unroll
                for (int ni = 0; ni < 4; ni++) {
                    mma16816(c[mi][ni], af[mi], bf[ni]);
                }
            }
        }
    }

    // epilogue
    const float* be = bias + (size_t)e * NDIM + f0;
    float bias0[4];
    float bias1[4];
#pragma unroll
    for (int ni = 0; ni < 4; ni++) {
        int col = wn + ni * 8 + (lane & 3) * 2;
        bias0[ni] = be[col];
        bias1[ni] = be[col + 1];
    }
#pragma unroll
    for (int mi = 0; mi < 4; mi++) {
#pragma unroll
        for (int hr = 0; hr < 2; hr++) {
            int rr = wm + mi * 16 + hr * 8 + (lane >> 2);
            int slot = rows_s[rr];
            if (slot >= 0) {
                if (GEMM1) {
                    __half* hp = g_h + (size_t)slot * NDIM + f0;
#pragma unroll
                    for (int ni = 0; ni < 4; ni++) {
                        int col = wn + ni * 8 + (lane & 3) * 2;
                        float v0 = fmaxf(c[mi][ni][hr * 2 + 0] + bias0[ni], 0.f);
                        float v1 = fmaxf(c[mi][ni][hr * 2 + 1] + bias1[ni], 0.f);
                        *(__half2*)(hp + col) = __floats2half2_rn(v0, v1);
                    }
                } else {
                    int tok = slot & (S_TOK - 1);
                    float w = g_sw[slot];
                    float* op = out + (size_t)tok * DM + f0;
#pragma unroll
                    for (int ni = 0; ni < 4; ni++) {
                        int col = wn + ni * 8 + (lane & 3) * 2;
                        atomicAdd(op + col,     w * (c[mi][ni][hr * 2 + 0] + bias0[ni]));
                        atomicAdd(op + col + 1, w * (c[mi][ni][hr * 2 + 1] + bias1[ni]));
                    }
                }
            }
        }
    }

    if (RESET) {
        __syncthreads();
        if (tid == 0) {
            int total = (int)(gridDim.x * gridDim.y * gridDim.z);
            int t = atomicAdd(&g_ticket, 1);
            if (t == total - 1) {
#pragma unroll
                for (int i = 0; i < NE; i++) g_count[i] = 0;
                g_ticket = 0;
            }
        }
    }
}

// ---------------------------------------------------------------------------
extern "C" void kernel_launch(void* const* d_in, const int* in_sizes, int n_in,
                              void* d_out, int out_size) {
    const float* x  = (const float*)d_in[0];
    const float* Wg = (const float*)d_in[1];
    const float* W1 = (const float*)d_in[2];
    const float* b1 = (const float*)d_in[3];
    const float* W2 = (const float*)d_in[4];
    const float* b2 = (const float*)d_in[5];
    float* out = (float*)d_out;

    const int smem = 2 * (BM * ASTR + BK * BSTR) * 2;   // 71680 B
    cudaFuncSetAttribute((const void*)moe_gemm<DM, DF, true, true, false>,
                         cudaFuncAttributeMaxDynamicSharedMemorySize, smem);
    cudaFuncSetAttribute((const void*)moe_gemm<DF, DM, false, false, true>,
                         cudaFuncAttributeMaxDynamicSharedMemorySize, smem);

    gate_prep_kernel<<<GATE_BLKS + CONV_BLKS, 256>>>(x, Wg, W1);
    moe_gemm<DM, DF, true, true, false>
        <<<dim3(DF / BN + W2_XTRA, NSLOT / BM, NE), 256, smem>>>(b1, out, W2);
    moe_gemm<DF, DM, false, false, true>
        <<<dim3(DM / BN, NSLOT / BM, NE), 256, smem>>>(b2, out, nullptr);
}

// round 16
// speedup vs baseline: 1.9876x; 1.9876x over previous
#include <cuda_runtime.h>
#include <cuda_fp16.h>
#include <cstdint>

// Problem constants
#define S_TOK   4096
#define NSLOT   8192
#define DM      768
#define DF      3072
#define NE      8

#define BM 128
#define BN 128
#define BK 64
#define ASTR 72            // A smem stride in halves
#define BSTR 136           // B smem stride in halves

#define N_OUT4 (S_TOK * DM / 4)
#define NW4    (NE * DM * DF / 4)

#define GATE_BLKS 512
#define CONV_BLKS 6144
#define W2_XTRA   4        // extra grid-x tiles on GEMM1 for W2 conversion + out zero

// ---- scratch (device globals; no allocation allowed) ----
__device__ int    g_count[NE];
__device__ int    g_ticket;
__device__ int    g_list[NE][NSLOT];
__device__ float  g_sw[NSLOT];
__device__ __half g_xh[(size_t)S_TOK * DM];
__device__ __half g_w1h[(size_t)NE * DM * DF];
__device__ __half g_w2h[(size_t)NE * DF * DM];
__device__ __half g_h[(size_t)NSLOT * DF];

__device__ __forceinline__ uint2 cvt4(const float4 v) {
    __half2 a = __floats2half2_rn(v.x, v.y);
    __half2 b = __floats2half2_rn(v.z, v.w);
    uint2 pk;
    pk.x = *(const unsigned*)&a;
    pk.y = *(const unsigned*)&b;
    return pk;
}

// ---------------------------------------------------------------------------
// fused gate(+inline x convert) + W1 convert
//   blocks [0, GATE_BLKS): gate, warp per token (original coalesced pattern;
//                          stores half(x) to g_xh inline, 2B/lane coalesced)
//   blocks [GATE_BLKS, ...): W1 f32->f16, consecutive float4 reads (coalesced)
// g_count is reset by GEMM2's tail ticket (zero-initialized on first call).
// ---------------------------------------------------------------------------
__global__ void __launch_bounds__(256) gate_prep_kernel(const float* __restrict__ x,
                                                        const float* __restrict__ Wg,
                                                        const float* __restrict__ W1) {
    if (blockIdx.x >= GATE_BLKS) {
        const int cb = blockIdx.x - GATE_BLKS;
        const int t0 = cb * 256 + threadIdx.x;
        const int NT = CONV_BLKS * 256;
#pragma unroll 4
        for (int i = t0; i < NW4; i += NT) {
            ((uint2*)g_w1h)[i] = cvt4(((const float4*)W1)[i]);
        }
        return;
    }

    int warp = threadIdx.x >> 5;
    int lane = threadIdx.x & 31;
    int s = blockIdx.x * 8 + warp;
    if (s >= S_TOK) return;

    const float* xr = x + (size_t)s * DM;
    __half* xh = g_xh + (size_t)s * DM;

    float acc[NE];
#pragma unroll
    for (int e = 0; e < NE; e++) acc[e] = 0.f;

#pragma unroll
    for (int i = 0; i < DM / 32; i++) {
        int m = lane + i * 32;
        float xv = xr[m];
        const float* wr = Wg + m * NE;
#pragma unroll
        for (int e = 0; e < NE; e++) acc[e] += xv * wr[e];
        xh[m] = __float2half(xv);          // inline f32->f16 of x (coalesced 2B)
    }
#pragma unroll
    for (int e = 0; e < NE; e++) {
#pragma unroll
        for (int o = 16; o > 0; o >>= 1) {
            acc[e] += __shfl_xor_sync(0xffffffffu, acc[e], o);
        }
    }

    if (lane == 0) {
        int a = 0;
#pragma unroll
        for (int e = 1; e < NE; e++) {
            if (acc[e] > acc[a]) a = e;
        }
        int b = (a == 0) ? 1 : 0;
#pragma unroll
        for (int e = 0; e < NE; e++) {
            if (e != a && acc[e] > acc[b]) b = e;
        }

        float eb = __expf(acc[b] - acc[a]);
        float inv = 1.f / (1.f + eb);
        g_sw[s] = inv;
        g_sw[S_TOK + s] = eb * inv;

        int pa = atomicAdd(&g_count[a], 1);
        g_list[a][pa] = s;
        int pb = atomicAdd(&g_count[b], 1);
        g_list[b][pb] = S_TOK + s;
    }
}

// ---------------------------------------------------------------------------
// tensor-core + cp.async helpers
// ---------------------------------------------------------------------------
__device__ __forceinline__ void ldsm_x4(unsigned& r0, unsigned& r1,
                                        unsigned& r2, unsigned& r3,
                                        const void* p) {
    unsigned a = (unsigned)__cvta_generic_to_shared(p);
    asm volatile("ldmatrix.sync.aligned.m8n8.x4.shared.b16 {%0,%1,%2,%3}, [%4];\n"
                 : "=r"(r0), "=r"(r1), "=r"(r2), "=r"(r3) : "r"(a));
}

__device__ __forceinline__ void ldsm_x4_t(unsigned& r0, unsigned& r1,
                                          unsigned& r2, unsigned& r3,
                                          const void* p) {
    unsigned a = (unsigned)__cvta_generic_to_shared(p);
    asm volatile("ldmatrix.sync.aligned.m8n8.x4.trans.shared.b16 {%0,%1,%2,%3}, [%4];\n"
                 : "=r"(r0), "=r"(r1), "=r"(r2), "=r"(r3) : "r"(a));
}

__device__ __forceinline__ void mma16816(float* c, const unsigned* a, const unsigned* b) {
    asm volatile(
        "mma.sync.aligned.m16n8k16.row.col.f32.f16.f16.f32 "
        "{%0,%1,%2,%3}, {%4,%5,%6,%7}, {%8,%9}, {%0,%1,%2,%3};\n"
        : "+f"(c[0]), "+f"(c[1]), "+f"(c[2]), "+f"(c[3])
        : "r"(a[0]), "r"(a[1]), "r"(a[2]), "r"(a[3]), "r"(b[0]), "r"(b[1]));
}

__device__ __forceinline__ void cp_async16(void* smem_ptr, const void* gptr, bool valid) {
    unsigned saddr = (unsigned)__cvta_generic_to_shared(smem_ptr);
    int sz = valid ? 16 : 0;
    asm volatile("cp.async.cg.shared.global [%0], [%1], 16, %2;\n"
                 :: "r"(saddr), "l"(gptr), "r"(sz));
}
__device__ __forceinline__ void cp_commit() {
    asm volatile("cp.async.commit_group;\n");
}
template<int N>
__device__ __forceinline__ void cp_wait() {
    asm volatile("cp.async.wait_group %0;\n" :: "n"(N));
}

// ---------------------------------------------------------------------------
// Grouped GEMM, 128x128x64 tile, 64x32 warp tiles, 2-stage pipeline, 2 CTA/SM.
//   GEMM1 (+FUSECONV): A = g_xh[slot & (S-1)], W = g_w1h -> relu -> g_h (half);
//                      extra grid-x blocks convert W2 f32->f16 and zero `out`.
//   GEMM2 (+RESET): A = g_h[slot], W = g_w2h -> w*(.+b2) atomicAdd -> out;
//                   last CTA (ticket) resets g_count for the next replay.
// ---------------------------------------------------------------------------
template<int KDIM, int NDIM, bool GEMM1, bool FUSECONV, bool RESET>
__global__ void __launch_bounds__(256, 2) moe_gemm(const float* __restrict__ bias,
                                                   float* __restrict__ out,
                                                   const float* __restrict__ wsrc) {
    constexpr int NTX = NDIM / BN;
    constexpr int A_ST_ELEM = BM * ASTR;
    constexpr int B_ST_ELEM = BK * BSTR;

    if (FUSECONV && blockIdx.x >= NTX) {
        // side-channel: W2 f32->f16 convert + zero `out` (overlaps GEMM1 compute)
        const int cid = ((blockIdx.x - NTX) * gridDim.y + blockIdx.y) * gridDim.z + blockIdx.z;
        const int t0 = cid * 256 + threadIdx.x;
        const int NT = W2_XTRA * (NSLOT / BM) * NE * 256;
#pragma unroll 4
        for (int i = t0; i < NW4; i += NT) {
            ((uint2*)g_w2h)[i] = cvt4(((const float4*)wsrc)[i]);
        }
#pragma unroll 4
        for (int i = t0; i < N_OUT4; i += NT) {
            ((float4*)out)[i] = make_float4(0.f, 0.f, 0.f, 0.f);
        }
        return;
    }

    const int e = blockIdx.z;
    const int cnt = g_count[e];
    const int row0 = blockIdx.y * BM;

    if (row0 >= cnt) {
        if (RESET) {
            if (threadIdx.x == 0) {
                int total = (int)(gridDim.x * gridDim.y * gridDim.z);
                int t = atomicAdd(&g_ticket, 1);
                if (t == total - 1) {
#pragma unroll
                    for (int i = 0; i < NE; i++) g_count[i] = 0;
                    g_ticket = 0;
                }
            }
        }
        return;
    }
    const int f0 = blockIdx.x * BN;

    extern __shared__ __half dyn[];
    __half* Asb = dyn;                        // [2][BM][ASTR]
    __half* Bsb = dyn + 2 * A_ST_ELEM;        // [2][BK][BSTR]
    __shared__ int rows_s[BM];

    const int tid = threadIdx.x;
    const int lane = tid & 31;
    const int wid = tid >> 5;
    const int wm = (wid >> 2) * 64;
    const int wn = (wid & 3) * 32;

    if (tid < BM) {
        int r = row0 + tid;
        rows_s[tid] = (r < cnt) ? g_list[e][r] : -1;
    }
    __syncthreads();

    const __half* Ab = GEMM1 ? g_xh : g_h;
    const __half* Wb = (GEMM1 ? g_w1h : g_w2h) + (size_t)e * KDIM * NDIM;

    int a_r[4], a_kq[4], a_slot[4];
#pragma unroll
    for (int l = 0; l < 4; l++) {
        int u = tid + l * 256;
        a_r[l] = u >> 3;
        a_kq[l] = u & 7;
        a_slot[l] = rows_s[a_r[l]];
    }
    int b_kr[4], b_cq[4];
#pragma unroll
    for (int l = 0; l < 4; l++) {
        int u = tid + l * 256;
        b_kr[l] = u >> 4;
        b_cq[l] = u & 15;
    }

    const int NK = KDIM / BK;

    auto load_tile = [&](int buf, int kt) {
        __half* As = Asb + buf * A_ST_ELEM;
        __half* Bs = Bsb + buf * B_ST_ELEM;
#pragma unroll
        for (int l = 0; l < 4; l++) {
            int slot = a_slot[l];
            const __half* src = Ab;
            bool v = (slot >= 0);
            if (v) {
                int arow = GEMM1 ? (slot & (S_TOK - 1)) : slot;
                src = Ab + (size_t)arow * KDIM + kt + a_kq[l] * 8;
            }
            cp_async16(As + a_r[l] * ASTR + a_kq[l] * 8, src, v);
        }
#pragma unroll
        for (int l = 0; l < 4; l++) {
            const __half* src = Wb + (size_t)(kt + b_kr[l]) * NDIM + f0 + b_cq[l] * 8;
            cp_async16(Bs + b_kr[l] * BSTR + b_cq[l] * 8, src, true);
        }
    };

    float c[4][4][4];
#pragma unroll
    for (int mi = 0; mi < 4; mi++) {
#pragma unroll
        for (int ni = 0; ni < 4; ni++) {
#pragma unroll
            for (int q = 0; q < 4; q++) {
                c[mi][ni][q] = 0.f;
            }
        }
    }

    load_tile(0, 0);
    cp_commit();

    for (int k = 0; k < NK; k++) {
        cp_wait<0>();
        __syncthreads();

        if (k + 1 < NK) {
            load_tile((k + 1) & 1, (k + 1) * BK);
            cp_commit();
        }

        const int buf = k & 1;
        const __half* As = Asb + buf * A_ST_ELEM;
        const __half* Bs = Bsb + buf * B_ST_ELEM;
#pragma unroll
        for (int kc = 0; kc < BK; kc += 16) {
            unsigned af[4][4];
            unsigned bf[4][2];
#pragma unroll
            for (int mi = 0; mi < 4; mi++) {
                ldsm_x4(af[mi][0], af[mi][1], af[mi][2], af[mi][3],
                        As + (wm + mi * 16 + (lane & 15)) * ASTR + kc + (lane >> 4) * 8);
            }
#pragma unroll
            for (int nj = 0; nj < 2; nj++) {
                ldsm_x4_t(bf[2 * nj][0], bf[2 * nj][1],
                          bf[2 * nj + 1][0], bf[2 * nj + 1][1],
                          Bs + (kc + (lane & 15)) * BSTR + wn + nj * 16 + (lane >> 4) * 8);
            }
#pragma unroll
            for (int mi = 0; mi < 4; mi++) {
#pragma unroll
                for (int ni = 0; ni < 4; ni++) {
                    mma16816(c[mi][ni], af[mi], bf[ni]);
                }
            }
        }
    }

    // epilogue
    const float* be = bias + (size_t)e * NDIM + f0;
    float bias0[4];
    float bias1[4];
#pragma unroll
    for (int ni = 0; ni < 4; ni++) {
        int col = wn + ni * 8 + (lane & 3) * 2;
        bias0[ni] = be[col];
        bias1[ni] = be[col + 1];
    }
#pragma unroll
    for (int mi = 0; mi < 4; mi++) {
#pragma unroll
        for (int hr = 0; hr < 2; hr++) {
            int rr = wm + mi * 16 + hr * 8 + (lane >> 2);
            int slot = rows_s[rr];
            if (slot >= 0) {
                if (GEMM1) {
                    __half* hp = g_h + (size_t)slot * NDIM + f0;
#pragma unroll
                    for (int ni = 0; ni < 4; ni++) {
                        int col = wn + ni * 8 + (lane & 3) * 2;
                        float v0 = fmaxf(c[mi][ni][hr * 2 + 0] + bias0[ni], 0.f);
                        float v1 = fmaxf(c[mi][ni][hr * 2 + 1] + bias1[ni], 0.f);
                        *(__half2*)(hp + col) = __floats2half2_rn(v0, v1);
                    }
                } else {
                    int tok = slot & (S_TOK - 1);
                    float w = g_sw[slot];
                    float* op = out + (size_t)tok * DM + f0;
#pragma unroll
                    for (int ni = 0; ni < 4; ni++) {
                        int col = wn + ni * 8 + (lane & 3) * 2;
                        atomicAdd(op + col,     w * (c[mi][ni][hr * 2 + 0] + bias0[ni]));
                        atomicAdd(op + col + 1, w * (c[mi][ni][hr * 2 + 1] + bias1[ni]));
                    }
                }
            }
        }
    }

    if (RESET) {
        __syncthreads();
        if (tid == 0) {
            int total = (int)(gridDim.x * gridDim.y * gridDim.z);
            int t = atomicAdd(&g_ticket, 1);
            if (t == total - 1) {
#pragma unroll
                for (int i = 0; i < NE; i++) g_count[i] = 0;
                g_ticket = 0;
            }
        }
    }
}

// ---------------------------------------------------------------------------
extern "C" void kernel_launch(void* const* d_in, const int* in_sizes, int n_in,
                              void* d_out, int out_size) {
    const float* x  = (const float*)d_in[0];
    const float* Wg = (const float*)d_in[1];
    const float* W1 = (const float*)d_in[2];
    const float* b1 = (const float*)d_in[3];
    const float* W2 = (const float*)d_in[4];
    const float* b2 = (const float*)d_in[5];
    float* out = (float*)d_out;

    const int smem = 2 * (BM * ASTR + BK * BSTR) * 2;   // 71680 B
    cudaFuncSetAttribute((const void*)moe_gemm<DM, DF, true, true, false>,
                         cudaFuncAttributeMaxDynamicSharedMemorySize, smem);
    cudaFuncSetAttribute((const void*)moe_gemm<DF, DM, false, false, true>,
                         cudaFuncAttributeMaxDynamicSharedMemorySize, smem);

    gate_prep_kernel<<<GATE_BLKS + CONV_BLKS, 256>>>(x, Wg, W1);
    moe_gemm<DM, DF, true, true, false>
        <<<dim3(DF / BN + W2_XTRA, NSLOT / BM, NE), 256, smem>>>(b1, out, W2);
    moe_gemm<DF, DM, false, false, true>
        <<<dim3(DM / BN, NSLOT / BM, NE), 256, smem>>>(b2, out, nullptr);
}

// round 17
// speedup vs baseline: 2.0643x; 1.0386x over previous
#include <cuda_runtime.h>
#include <cuda_fp16.h>
#include <cstdint>

// Problem constants
#define S_TOK   4096
#define NSLOT   8192
#define DM      768
#define DF      3072
#define NE      8

#define BM 128
#define BN 128
#define BK 64
#define ASTR 72            // A smem stride in halves
#define BSTR 136           // B smem stride in halves

#define N_OUT4 (S_TOK * DM / 4)
#define NW4    (NE * DM * DF / 4)

#define GATE_BLKS 512
#define CONV_BLKS 6144
#define W2_XTRA   4        // extra grid-x tiles on GEMM1 for W2 conversion + out zero

// ---- scratch (device globals; no allocation allowed) ----
__device__ int    g_count[NE];
__device__ int    g_ticket;
__device__ int    g_list[NE][NSLOT];
__device__ float  g_sw[NSLOT];
__device__ __half g_xh[(size_t)S_TOK * DM];
__device__ __half g_w1h[(size_t)NE * DM * DF];
__device__ __half g_w2h[(size_t)NE * DF * DM];
__device__ __half g_h[(size_t)NSLOT * DF];

__device__ __forceinline__ uint2 cvt4(const float4 v) {
    __half2 a = __floats2half2_rn(v.x, v.y);
    __half2 b = __floats2half2_rn(v.z, v.w);
    uint2 pk;
    pk.x = *(const unsigned*)&a;
    pk.y = *(const unsigned*)&b;
    return pk;
}

// ---------------------------------------------------------------------------
// fused gate(+inline x convert) + W1 convert
//   blocks [0, GATE_BLKS): gate, warp per token; Wg row read as 2x float4
//   blocks [GATE_BLKS, ...): W1 f32->f16, consecutive float4 reads (coalesced)
// g_count is reset by GEMM2's tail ticket (zero-initialized on first call).
// ---------------------------------------------------------------------------
__global__ void __launch_bounds__(256) gate_prep_kernel(const float* __restrict__ x,
                                                        const float* __restrict__ Wg,
                                                        const float* __restrict__ W1) {
    if (blockIdx.x >= GATE_BLKS) {
        const int cb = blockIdx.x - GATE_BLKS;
        const int t0 = cb * 256 + threadIdx.x;
        const int NT = CONV_BLKS * 256;
#pragma unroll 4
        for (int i = t0; i < NW4; i += NT) {
            ((uint2*)g_w1h)[i] = cvt4(((const float4*)W1)[i]);
        }
        return;
    }

    int warp = threadIdx.x >> 5;
    int lane = threadIdx.x & 31;
    int s = blockIdx.x * 8 + warp;
    if (s >= S_TOK) return;

    const float* xr = x + (size_t)s * DM;
    __half* xh = g_xh + (size_t)s * DM;

    float acc[NE];
#pragma unroll
    for (int e = 0; e < NE; e++) acc[e] = 0.f;

#pragma unroll
    for (int i = 0; i < DM / 32; i++) {
        int m = lane + i * 32;
        float xv = xr[m];
        // Wg row for element m: 8 contiguous floats -> two float4 loads
        const float4* wr4 = (const float4*)(Wg + m * NE);
        float4 w0 = wr4[0];
        float4 w1 = wr4[1];
        acc[0] += xv * w0.x;
        acc[1] += xv * w0.y;
        acc[2] += xv * w0.z;
        acc[3] += xv * w0.w;
        acc[4] += xv * w1.x;
        acc[5] += xv * w1.y;
        acc[6] += xv * w1.z;
        acc[7] += xv * w1.w;
        xh[m] = __float2half(xv);          // inline f32->f16 of x (coalesced 2B)
    }
#pragma unroll
    for (int e = 0; e < NE; e++) {
#pragma unroll
        for (int o = 16; o > 0; o >>= 1) {
            acc[e] += __shfl_xor_sync(0xffffffffu, acc[e], o);
        }
    }

    if (lane == 0) {
        int a = 0;
#pragma unroll
        for (int e = 1; e < NE; e++) {
            if (acc[e] > acc[a]) a = e;
        }
        int b = (a == 0) ? 1 : 0;
#pragma unroll
        for (int e = 0; e < NE; e++) {
            if (e != a && acc[e] > acc[b]) b = e;
        }

        float eb = __expf(acc[b] - acc[a]);
        float inv = 1.f / (1.f + eb);
        g_sw[s] = inv;
        g_sw[S_TOK + s] = eb * inv;

        int pa = atomicAdd(&g_count[a], 1);
        g_list[a][pa] = s;
        int pb = atomicAdd(&g_count[b], 1);
        g_list[b][pb] = S_TOK + s;
    }
}

// ---------------------------------------------------------------------------
// tensor-core + cp.async helpers
// ---------------------------------------------------------------------------
__device__ __forceinline__ void ldsm_x4(unsigned& r0, unsigned& r1,
                                        unsigned& r2, unsigned& r3,
                                        const void* p) {
    unsigned a = (unsigned)__cvta_generic_to_shared(p);
    asm volatile("ldmatrix.sync.aligned.m8n8.x4.shared.b16 {%0,%1,%2,%3}, [%4];\n"
                 : "=r"(r0), "=r"(r1), "=r"(r2), "=r"(r3) : "r"(a));
}

__device__ __forceinline__ void ldsm_x4_t(unsigned& r0, unsigned& r1,
                                          unsigned& r2, unsigned& r3,
                                          const void* p) {
    unsigned a = (unsigned)__cvta_generic_to_shared(p);
    asm volatile("ldmatrix.sync.aligned.m8n8.x4.trans.shared.b16 {%0,%1,%2,%3}, [%4];\n"
                 : "=r"(r0), "=r"(r1), "=r"(r2), "=r"(r3) : "r"(a));
}

__device__ __forceinline__ void mma16816(float* c, const unsigned* a, const unsigned* b) {
    asm volatile(
        "mma.sync.aligned.m16n8k16.row.col.f32.f16.f16.f32 "
        "{%0,%1,%2,%3}, {%4,%5,%6,%7}, {%8,%9}, {%0,%1,%2,%3};\n"
        : "+f"(c[0]), "+f"(c[1]), "+f"(c[2]), "+f"(c[3])
        : "r"(a[0]), "r"(a[1]), "r"(a[2]), "r"(a[3]), "r"(b[0]), "r"(b[1]));
}

__device__ __forceinline__ void cp_async16(void* smem_ptr, const void* gptr, bool valid) {
    unsigned saddr = (unsigned)__cvta_generic_to_shared(smem_ptr);
    int sz = valid ? 16 : 0;
    asm volatile("cp.async.cg.shared.global [%0], [%1], 16, %2;\n"
                 :: "r"(saddr), "l"(gptr), "r"(sz));
}
__device__ __forceinline__ void cp_commit() {
    asm volatile("cp.async.commit_group;\n");
}
template<int N>
__device__ __forceinline__ void cp_wait() {
    asm volatile("cp.async.wait_group %0;\n" :: "n"(N));
}

// ---------------------------------------------------------------------------
// Grouped GEMM, 128x128x64 tile, 64x32 warp tiles, 2-stage pipeline, 2 CTA/SM.
//   GEMM1 (+FUSECONV): A = g_xh[slot & (S-1)], W = g_w1h -> relu -> g_h (half);
//                      extra grid-x blocks convert W2 f32->f16 and zero `out`.
//   GEMM2 (+RESET): A = g_h[slot], W = g_w2h -> w*(.+b2) atomicAdd -> out;
//                   last CTA (ticket) resets g_count for the next replay.
// ---------------------------------------------------------------------------
template<int KDIM, int NDIM, bool GEMM1, bool FUSECONV, bool RESET>
__global__ void __launch_bounds__(256, 2) moe_gemm(const float* __restrict__ bias,
                                                   float* __restrict__ out,
                                                   const float* __restrict__ wsrc) {
    constexpr int NTX = NDIM / BN;
    constexpr int A_ST_ELEM = BM * ASTR;
    constexpr int B_ST_ELEM = BK * BSTR;

    if (FUSECONV && blockIdx.x >= NTX) {
        // side-channel: W2 f32->f16 convert + zero `out` (overlaps GEMM1 compute)
        const int cid = ((blockIdx.x - NTX) * gridDim.y + blockIdx.y) * gridDim.z + blockIdx.z;
        const int t0 = cid * 256 + threadIdx.x;
        const int NT = W2_XTRA * (NSLOT / BM) * NE * 256;
#pragma unroll 4
        for (int i = t0; i < NW4; i += NT) {
            ((uint2*)g_w2h)[i] = cvt4(((const float4*)wsrc)[i]);
        }
#pragma unroll 4
        for (int i = t0; i < N_OUT4; i += NT) {
            ((float4*)out)[i] = make_float4(0.f, 0.f, 0.f, 0.f);
        }
        return;
    }

    const int e = blockIdx.z;
    const int cnt = g_count[e];
    const int row0 = blockIdx.y * BM;

    if (row0 >= cnt) {
        if (RESET) {
            if (threadIdx.x == 0) {
                int total = (int)(gridDim.x * gridDim.y * gridDim.z);
                int t = atomicAdd(&g_ticket, 1);
                if (t == total - 1) {
#pragma unroll
                    for (int i = 0; i < NE; i++) g_count[i] = 0;
                    g_ticket = 0;
                }
            }
        }
        return;
    }
    const int f0 = blockIdx.x * BN;

    extern __shared__ __half dyn[];
    __half* Asb = dyn;                        // [2][BM][ASTR]
    __half* Bsb = dyn + 2 * A_ST_ELEM;        // [2][BK][BSTR]
    __shared__ int rows_s[BM];

    const int tid = threadIdx.x;
    const int lane = tid & 31;
    const int wid = tid >> 5;
    const int wm = (wid >> 2) * 64;
    const int wn = (wid & 3) * 32;

    if (tid < BM) {
        int r = row0 + tid;
        rows_s[tid] = (r < cnt) ? g_list[e][r] : -1;
    }
    __syncthreads();

    const __half* Ab = GEMM1 ? g_xh : g_h;
    const __half* Wb = (GEMM1 ? g_w1h : g_w2h) + (size_t)e * KDIM * NDIM;

    int a_r[4], a_kq[4], a_slot[4];
#pragma unroll
    for (int l = 0; l < 4; l++) {
        int u = tid + l * 256;
        a_r[l] = u >> 3;
        a_kq[l] = u & 7;
        a_slot[l] = rows_s[a_r[l]];
    }
    int b_kr[4], b_cq[4];
#pragma unroll
    for (int l = 0; l < 4; l++) {
        int u = tid + l * 256;
        b_kr[l] = u >> 4;
        b_cq[l] = u & 15;
    }

    const int NK = KDIM / BK;

    auto load_tile = [&](int buf, int kt) {
        __half* As = Asb + buf * A_ST_ELEM;
        __half* Bs = Bsb + buf * B_ST_ELEM;
#pragma unroll
        for (int l = 0; l < 4; l++) {
            int slot = a_slot[l];
            const __half* src = Ab;
            bool v = (slot >= 0);
            if (v) {
                int arow = GEMM1 ? (slot & (S_TOK - 1)) : slot;
                src = Ab + (size_t)arow * KDIM + kt + a_kq[l] * 8;
            }
            cp_async16(As + a_r[l] * ASTR + a_kq[l] * 8, src, v);
        }
#pragma unroll
        for (int l = 0; l < 4; l++) {
            const __half* src = Wb + (size_t)(kt + b_kr[l]) * NDIM + f0 + b_cq[l] * 8;
            cp_async16(Bs + b_kr[l] * BSTR + b_cq[l] * 8, src, true);
        }
    };

    float c[4][4][4];
#pragma unroll
    for (int mi = 0; mi < 4; mi++) {
#pragma unroll
        for (int ni = 0; ni < 4; ni++) {
#pragma unroll
            for (int q = 0; q < 4; q++) {
                c[mi][ni][q] = 0.f;
            }
        }
    }

    load_tile(0, 0);
    cp_commit();

    for (int k = 0; k < NK; k++) {
        cp_wait<0>();
        __syncthreads();

        if (k + 1 < NK) {
            load_tile((k + 1) & 1, (k + 1) * BK);
            cp_commit();
        }

        const int buf = k & 1;
        const __half* As = Asb + buf * A_ST_ELEM;
        const __half* Bs = Bsb + buf * B_ST_ELEM;
#pragma unroll
        for (int kc = 0; kc < BK; kc += 16) {
            unsigned af[4][4];
            unsigned bf[4][2];
#pragma unroll
            for (int mi = 0; mi < 4; mi++) {
                ldsm_x4(af[mi][0], af[mi][1], af[mi][2], af[mi][3],
                        As + (wm + mi * 16 + (lane & 15)) * ASTR + kc + (lane >> 4) * 8);
            }
#pragma unroll
            for (int nj = 0; nj < 2; nj++) {
                ldsm_x4_t(bf[2 * nj][0], bf[2 * nj][1],
                          bf[2 * nj + 1][0], bf[2 * nj + 1][1],
                          Bs + (kc + (lane & 15)) * BSTR + wn + nj * 16 + (lane >> 4) * 8);
            }
#pragma unroll
            for (int mi = 0; mi < 4; mi++) {
#pragma unroll
                for (int ni = 0; ni < 4; ni++) {
                    mma16816(c[mi][ni], af[mi], bf[ni]);
                }
            }
        }
    }

    // epilogue
    const float* be = bias + (size_t)e * NDIM + f0;
    float bias0[4];
    float bias1[4];
#pragma unroll
    for (int ni = 0; ni < 4; ni++) {
        int col = wn + ni * 8 + (lane & 3) * 2;
        bias0[ni] = be[col];
        bias1[ni] = be[col + 1];
    }
#pragma unroll
    for (int mi = 0; mi < 4; mi++) {
#pragma unroll
        for (int hr = 0; hr < 2; hr++) {
            int rr = wm + mi * 16 + hr * 8 + (lane >> 2);
            int slot = rows_s[rr];
            if (slot >= 0) {
                if (GEMM1) {
                    __half* hp = g_h + (size_t)slot * NDIM + f0;
#pragma unroll
                    for (int ni = 0; ni < 4; ni++) {
                        int col = wn + ni * 8 + (lane & 3) * 2;
                        float v0 = fmaxf(c[mi][ni][hr * 2 + 0] + bias0[ni], 0.f);
                        float v1 = fmaxf(c[mi][ni][hr * 2 + 1] + bias1[ni], 0.f);
                        *(__half2*)(hp + col) = __floats2half2_rn(v0, v1);
                    }
                } else {
                    int tok = slot & (S_TOK - 1);
                    float w = g_sw[slot];
                    float* op = out + (size_t)tok * DM + f0;
#pragma unroll
                    for (int ni = 0; ni < 4; ni++) {
                        int col = wn + ni * 8 + (lane & 3) * 2;
                        atomicAdd(op + col,     w * (c[mi][ni][hr * 2 + 0] + bias0[ni]));
                        atomicAdd(op + col + 1, w * (c[mi][ni][hr * 2 + 1] + bias1[ni]));
                    }
                }
            }
        }
    }

    if (RESET) {
        __syncthreads();
        if (tid == 0) {
            int total = (int)(gridDim.x * gridDim.y * gridDim.z);
            int t = atomicAdd(&g_ticket, 1);
            if (t == total - 1) {
#pragma unroll
                for (int i = 0; i < NE; i++) g_count[i] = 0;
                g_ticket = 0;
            }
        }
    }
}

// ---------------------------------------------------------------------------
extern "C" void kernel_launch(void* const* d_in, const int* in_sizes, int n_in,
                              void* d_out, int out_size) {
    const float* x  = (const float*)d_in[0];
    const float* Wg = (const float*)d_in[1];
    const float* W1 = (const float*)d_in[2];
    const float* b1 = (const float*)d_in[3];
    const float* W2 = (const float*)d_in[4];
    const float* b2 = (const float*)d_in[5];
    float* out = (float*)d_out;

    const int smem = 2 * (BM * ASTR + BK * BSTR) * 2;   // 71680 B
    cudaFuncSetAttribute((const void*)moe_gemm<DM, DF, true, true, false>,
                         cudaFuncAttributeMaxDynamicSharedMemorySize, smem);
    cudaFuncSetAttribute((const void*)moe_gemm<DF, DM, false, false, true>,
                         cudaFuncAttributeMaxDynamicSharedMemorySize, smem);

    gate_prep_kernel<<<GATE_BLKS + CONV_BLKS, 256>>>(x, Wg, W1);
    moe_gemm<DM, DF, true, true, false>
        <<<dim3(DF / BN + W2_XTRA, NSLOT / BM, NE), 256, smem>>>(b1, out, W2);
    moe_gemm<DF, DM, false, false, true>
        <<<dim3(DM / BN, NSLOT / BM, NE), 256, smem>>>(b2, out, nullptr);
}